// round 6
// baseline (speedup 1.0000x reference)
#include <cuda_runtime.h>

typedef unsigned long long ull;

#define NN 50000
#define DD 128
#define EE 1600000
#define TWO_N (2*NN)
#define SCAN_B 512
#define NSB ((TWO_N + SCAN_B - 1)/SCAN_B)
#define TILE_R 64
#define NBLK ((NN + TILE_R - 1)/TILE_R)
#define PAD 68     // transposed tile pad (words), multiple of 4
#define RMP 132    // row-major pad
#define GT 256     // GEMM kernel threads (8 warps)

// ---------------- f32x2 packed-math helpers ----------------
__device__ __forceinline__ ull bcast2(float x) {
    ull r; asm("mov.b64 %0, {%1,%1};" : "=l"(r) : "f"(x)); return r;
}
__device__ __forceinline__ ull pack2f(float lo, float hi) {
    ull r; asm("mov.b64 %0, {%1,%2};" : "=l"(r) : "f"(lo), "f"(hi)); return r;
}
__device__ __forceinline__ void ffma2(ull& d, ull a, ull b) {
    asm("fma.rn.f32x2 %0, %1, %2, %0;" : "+l"(d) : "l"(a), "l"(b));
}
__device__ __forceinline__ float2 unpack2(ull v) {
    float2 f; asm("mov.b64 {%0,%1}, %2;" : "=f"(f.x), "=f"(f.y) : "l"(v)); return f;
}

// ---------------- scratch ----------------
__device__ int   g_cnt[TWO_N];
__device__ int   g_off[TWO_N + 1];
__device__ int   g_bsum[NSB];
__device__ int   g_col[2*EE];
__device__ float g_ua[NN*DD];   // ua, later reused as phase-A partial (t + gin_a + b2a)
__device__ float g_ub[NN*DD];

// ---------------- CSR construction ----------------
__global__ void zero_cnt_kernel() {
    int i = blockIdx.x*blockDim.x + threadIdx.x;
    if (i < TWO_N) g_cnt[i] = 0;
}

__global__ void hist_kernel(const int* __restrict__ et, const int* __restrict__ ex) {
    int i = blockIdx.x*blockDim.x + threadIdx.x;
    if (i < EE) {
        atomicAdd(&g_cnt[et[EE + i]], 1);
        atomicAdd(&g_cnt[NN + ex[EE + i]], 1);
    }
}

__global__ void scan1_kernel() {
    __shared__ int s[SCAN_B];
    int i = blockIdx.x*SCAN_B + threadIdx.x;
    int v = (i < TWO_N) ? g_cnt[i] : 0;
    s[threadIdx.x] = v;
    __syncthreads();
    #pragma unroll
    for (int d = 1; d < SCAN_B; d <<= 1) {
        int tv = (threadIdx.x >= d) ? s[threadIdx.x - d] : 0;
        __syncthreads();
        s[threadIdx.x] += tv;
        __syncthreads();
    }
    if (i < TWO_N) g_off[i + 1] = s[threadIdx.x];
    if (threadIdx.x == SCAN_B - 1) g_bsum[blockIdx.x] = s[SCAN_B - 1];
}

__global__ void scan2_kernel() {
    __shared__ int s[256];
    int v = (threadIdx.x < NSB) ? g_bsum[threadIdx.x] : 0;
    s[threadIdx.x] = v;
    __syncthreads();
    #pragma unroll
    for (int d = 1; d < 256; d <<= 1) {
        int tv = (threadIdx.x >= d) ? s[threadIdx.x - d] : 0;
        __syncthreads();
        s[threadIdx.x] += tv;
        __syncthreads();
    }
    if (threadIdx.x < NSB) g_bsum[threadIdx.x] = s[threadIdx.x] - v;
}

__global__ void scan3_kernel() {
    int i = blockIdx.x*blockDim.x + threadIdx.x;
    if (i == 0) { g_off[0] = 0; g_cnt[0] = 0; }
    else if (i <= TWO_N) {
        int v = g_off[i] + g_bsum[(i - 1) / SCAN_B];
        g_off[i] = v;
        if (i < TWO_N) g_cnt[i] = v;
    }
}

__global__ void fill_kernel(const int* __restrict__ et, const int* __restrict__ ex) {
    int i = blockIdx.x*blockDim.x + threadIdx.x;
    if (i < EE) {
        int p = atomicAdd(&g_cnt[et[EE + i]], 1);
        g_col[p] = et[i];
        int q = atomicAdd(&g_cnt[NN + ex[EE + i]], 1);
        g_col[q] = ex[i];
    }
}

// ---------------- aggregation: warp per destination node ----------------
__global__ void agg_kernel(const float* __restrict__ x, const float* __restrict__ t,
                           float* __restrict__ ua, float* __restrict__ ub) {
    int warp = (blockIdx.x*blockDim.x + threadIdx.x) >> 5;
    int lane = threadIdx.x & 31;
    if (warp >= NN) return;
    const float4* t4 = (const float4*)t;
    const float4* x4 = (const float4*)x;

    float4 base = t4[warp*32 + lane];
    float4 aA = base, aB = base;

    int e  = g_off[warp],      eE = g_off[warp + 1];
    for (; e + 1 < eE; e += 2) {
        int s0 = g_col[e], s1 = g_col[e + 1];
        float4 v0 = t4[s0*32 + lane];
        float4 v1 = t4[s1*32 + lane];
        aA.x += v0.x; aA.y += v0.y; aA.z += v0.z; aA.w += v0.w;
        aA.x += v1.x; aA.y += v1.y; aA.z += v1.z; aA.w += v1.w;
    }
    if (e < eE) {
        int s0 = g_col[e];
        float4 v0 = t4[s0*32 + lane];
        aA.x += v0.x; aA.y += v0.y; aA.z += v0.z; aA.w += v0.w;
    }

    e = g_off[NN + warp]; eE = g_off[NN + warp + 1];
    for (; e + 1 < eE; e += 2) {
        int s0 = g_col[e], s1 = g_col[e + 1];
        float4 v0 = x4[s0*32 + lane];
        float4 v1 = x4[s1*32 + lane];
        aB.x += v0.x; aB.y += v0.y; aB.z += v0.z; aB.w += v0.w;
        aB.x += v1.x; aB.y += v1.y; aB.z += v1.z; aB.w += v1.w;
    }
    if (e < eE) {
        int s0 = g_col[e];
        float4 v0 = x4[s0*32 + lane];
        aB.x += v0.x; aB.y += v0.y; aB.z += v0.z; aB.w += v0.w;
    }

    ((float4*)ua)[warp*32 + lane] = aA;
    ((float4*)ub)[warp*32 + lane] = aB;
}

// ================= GEMM building blocks (256 threads: 8 rows x 4 cols each) ====
// layer over transposed tile sIn[128][PAD]: two aligned b64x2 broadcast loads = 8 rows
__device__ __forceinline__ void gemm_layer_T(const float* __restrict__ sIn,
                                             const float* __restrict__ sW,
                                             int rb, int tc, ull acc[4][4]) {
    #pragma unroll 2
    for (int k = 0; k < 128; k++) {
        ulonglong2 A0 = *(const ulonglong2*)&sIn[k*PAD + rb];       // rows rb..rb+3
        ulonglong2 A1 = *(const ulonglong2*)&sIn[k*PAD + rb + 4];   // rows rb+4..rb+7
        float4 bv = *(const float4*)(sW + k*128 + tc*4);
        ull b0 = bcast2(bv.x), b1 = bcast2(bv.y), b2 = bcast2(bv.z), b3 = bcast2(bv.w);
        ull ap0 = A0.x, ap1 = A0.y, ap2 = A1.x, ap3 = A1.y;
        ffma2(acc[0][0], ap0, b0); ffma2(acc[0][1], ap0, b1); ffma2(acc[0][2], ap0, b2); ffma2(acc[0][3], ap0, b3);
        ffma2(acc[1][0], ap1, b0); ffma2(acc[1][1], ap1, b1); ffma2(acc[1][2], ap1, b2); ffma2(acc[1][3], ap1, b3);
        ffma2(acc[2][0], ap2, b0); ffma2(acc[2][1], ap2, b1); ffma2(acc[2][2], ap2, b2); ffma2(acc[2][3], ap2, b3);
        ffma2(acc[3][0], ap3, b0); ffma2(acc[3][1], ap3, b1); ffma2(acc[3][2], ap3, b2); ffma2(acc[3][3], ap3, b3);
    }
}

// layer over row-major tile sIn[64][RMP]: 8 broadcast scalar loads + packs
__device__ __forceinline__ void gemm_layer_rm(const float* __restrict__ sIn,
                                              const float* __restrict__ sW,
                                              int rb, int tc, ull acc[4][4]) {
    const float* base = sIn + rb*RMP;
    #pragma unroll 2
    for (int k = 0; k < 128; k++) {
        float h0 = base[0*RMP + k], h1 = base[1*RMP + k];
        float h2 = base[2*RMP + k], h3 = base[3*RMP + k];
        float h4 = base[4*RMP + k], h5 = base[5*RMP + k];
        float h6 = base[6*RMP + k], h7 = base[7*RMP + k];
        ull ap0 = pack2f(h0, h1), ap1 = pack2f(h2, h3);
        ull ap2 = pack2f(h4, h5), ap3 = pack2f(h6, h7);
        float4 bv = *(const float4*)(sW + k*128 + tc*4);
        ull b0 = bcast2(bv.x), b1 = bcast2(bv.y), b2 = bcast2(bv.z), b3 = bcast2(bv.w);
        ffma2(acc[0][0], ap0, b0); ffma2(acc[0][1], ap0, b1); ffma2(acc[0][2], ap0, b2); ffma2(acc[0][3], ap0, b3);
        ffma2(acc[1][0], ap1, b0); ffma2(acc[1][1], ap1, b1); ffma2(acc[1][2], ap1, b2); ffma2(acc[1][3], ap1, b3);
        ffma2(acc[2][0], ap2, b0); ffma2(acc[2][1], ap2, b1); ffma2(acc[2][2], ap2, b2); ffma2(acc[2][3], ap2, b3);
        ffma2(acc[3][0], ap3, b0); ffma2(acc[3][1], ap3, b1); ffma2(acc[3][2], ap3, b2); ffma2(acc[3][3], ap3, b3);
    }
}

__device__ __forceinline__ void zero_acc(ull acc[4][4]) {
    #pragma unroll
    for (int p = 0; p < 4; p++)
        #pragma unroll
        for (int c = 0; c < 4; c++) acc[p][c] = 0ull;
}

// bias+relu epilogue -> row-major smem buffer (conflict-free float4 stores)
__device__ __forceinline__ void relu_store_rm(const ull acc[4][4], float4 bv,
                                              float* __restrict__ sOut, int rb, int tc) {
    #pragma unroll
    for (int p = 0; p < 4; p++) {
        float2 v0 = unpack2(acc[p][0]);
        float2 v1 = unpack2(acc[p][1]);
        float2 v2 = unpack2(acc[p][2]);
        float2 v3 = unpack2(acc[p][3]);
        float4 lo, hi;
        lo.x = fmaxf(v0.x + bv.x, 0.f); hi.x = fmaxf(v0.y + bv.x, 0.f);
        lo.y = fmaxf(v1.x + bv.y, 0.f); hi.y = fmaxf(v1.y + bv.y, 0.f);
        lo.z = fmaxf(v2.x + bv.z, 0.f); hi.z = fmaxf(v2.y + bv.z, 0.f);
        lo.w = fmaxf(v3.x + bv.w, 0.f); hi.w = fmaxf(v3.y + bv.w, 0.f);
        *(float4*)&sOut[(rb + 2*p)*RMP + tc*4]     = lo;
        *(float4*)&sOut[(rb + 2*p + 1)*RMP + tc*4] = hi;
    }
}

__device__ __forceinline__ void load_tileT(float* __restrict__ sAT,
                                           const float* __restrict__ A,
                                           int row0, int tid) {
    #pragma unroll
    for (int idx = tid; idx < TILE_R*128; idx += GT) {
        int r = idx >> 7, k = idx & 127;
        int row = row0 + r;
        sAT[k*PAD + r] = (row < NN) ? A[(size_t)row*128 + k] : 0.f;
    }
}

__device__ __forceinline__ void copy_w(float* __restrict__ dst,
                                       const float* __restrict__ src, int tid) {
    const float4* s4 = (const float4*)src;
    float4* d4 = (float4*)dst;
    #pragma unroll
    for (int i = tid; i < 4096; i += GT) d4[i] = s4[i];
}

// smem: sW(16384) + region(128*PAD = 8704; holds A^T then H/t2 row-major [64][RMP]=8448)
#define SMEM_G_FLOATS (16384 + 128*PAD)
#define SMEM_G_BYTES  (SMEM_G_FLOATS * 4)

// ================= fc_x: x_out = x + relu(x@Wf1+bf1)@Wf2 + bf2 =================
__global__ __launch_bounds__(GT, 2) void fc_x_kernel(
    const float* __restrict__ X,
    const float* __restrict__ W1, const float* __restrict__ B1,
    const float* __restrict__ W2, const float* __restrict__ B2,
    float* __restrict__ OUT)
{
    extern __shared__ float sm[];
    float* sW  = sm;            // staged weight
    float* sRG = sm + 16384;    // A^T [128][PAD], then H [64][RMP]

    const int tid = threadIdx.x;
    const int tc = tid & 31;
    const int rb = (tid >> 5) * 8;      // 8 warps * 8 rows = 64
    const int row0 = blockIdx.x * TILE_R;

    float4 vb1 = ((const float4*)B1)[tc];
    float4 vb2 = ((const float4*)B2)[tc];

    copy_w(sW, W1, tid);
    load_tileT(sRG, X, row0, tid);
    __syncthreads();

    ull acc[4][4];
    zero_acc(acc);
    gemm_layer_T(sRG, sW, rb, tc, acc);
    __syncthreads();                        // everyone done reading A^T

    relu_store_rm(acc, vb1, sRG, rb, tc);   // H overwrites A^T region
    copy_w(sW, W2, tid);
    __syncthreads();

    zero_acc(acc);
    gemm_layer_rm(sRG, sW, rb, tc, acc);

    #pragma unroll
    for (int p = 0; p < 4; p++) {
        float2 v0 = unpack2(acc[p][0]);
        float2 v1 = unpack2(acc[p][1]);
        float2 v2 = unpack2(acc[p][2]);
        float2 v3 = unpack2(acc[p][3]);
        #pragma unroll
        for (int q = 0; q < 2; q++) {
            int row = row0 + rb + 2*p + q;
            if (row < NN) {
                float4 xv = ((const float4*)X)[(size_t)row*32 + tc];
                float4 o;
                o.x = xv.x + (q ? v0.y : v0.x) + vb2.x;
                o.y = xv.y + (q ? v1.y : v1.x) + vb2.y;
                o.z = xv.z + (q ? v2.y : v2.x) + vb2.z;
                o.w = xv.w + (q ? v3.y : v3.x) + vb2.w;
                ((float4*)OUT)[(size_t)row*32 + tc] = o;
            }
        }
    }
}

// ================= fused t-branch =================
// t2 = relu(t + mlp_a(ua) + mlp_b(ub));  t_out = t2 + LN(relu(t2@Wo+bo))*g + b
// phase-A partial (t + gin_a + b2a) spills to g_ua (same rows this block owns).
__global__ __launch_bounds__(GT, 2) void fused_t_kernel(
    float* __restrict__ ua,             // consumed, then reused as partial buffer
    const float* __restrict__ ub,
    const float* __restrict__ t,
    const float* __restrict__ W1a, const float* __restrict__ b1a,
    const float* __restrict__ W2a, const float* __restrict__ b2a,
    const float* __restrict__ W1b, const float* __restrict__ b1b,
    const float* __restrict__ W2b, const float* __restrict__ b2b,
    const float* __restrict__ Wo,  const float* __restrict__ bo,
    const float* __restrict__ lng, const float* __restrict__ lnb,
    float* __restrict__ OUT)
{
    extern __shared__ float sm[];
    float* sW  = sm;            // staged weight
    float* sRG = sm + 16384;    // A^T [128][PAD] / H,t2 [64][RMP]

    const int tid = threadIdx.x;
    const int tc  = tid & 31;
    const int rb  = (tid >> 5) * 8;
    const int row0 = blockIdx.x * TILE_R;

    float4 vb1a = ((const float4*)b1a)[tc];
    float4 vb2a = ((const float4*)b2a)[tc];
    float4 vb1b = ((const float4*)b1b)[tc];
    float4 vb2b = ((const float4*)b2b)[tc];
    float4 vbo  = ((const float4*)bo)[tc];
    float4 vg   = ((const float4*)lng)[tc];
    float4 vbe  = ((const float4*)lnb)[tc];

    ull acc[4][4];

    // ---- phase A: gin_a(ua); partial = t + ga + b2a -> g_ua ----
    copy_w(sW, W1a, tid);
    load_tileT(sRG, ua, row0, tid);
    __syncthreads();

    zero_acc(acc);
    gemm_layer_T(sRG, sW, rb, tc, acc);
    __syncthreads();

    relu_store_rm(acc, vb1a, sRG, rb, tc);
    copy_w(sW, W2a, tid);
    __syncthreads();

    zero_acc(acc);
    gemm_layer_rm(sRG, sW, rb, tc, acc);

    #pragma unroll
    for (int p = 0; p < 4; p++) {
        float2 v0 = unpack2(acc[p][0]);
        float2 v1 = unpack2(acc[p][1]);
        float2 v2 = unpack2(acc[p][2]);
        float2 v3 = unpack2(acc[p][3]);
        #pragma unroll
        for (int q = 0; q < 2; q++) {
            int row = row0 + rb + 2*p + q;
            if (row < NN) {
                float4 tv = ((const float4*)t)[(size_t)row*32 + tc];
                float4 o;
                o.x = tv.x + (q ? v0.y : v0.x) + vb2a.x;
                o.y = tv.y + (q ? v1.y : v1.x) + vb2a.y;
                o.z = tv.z + (q ? v2.y : v2.x) + vb2a.z;
                o.w = tv.w + (q ? v3.y : v3.x) + vb2a.w;
                ((float4*)ua)[(size_t)row*32 + tc] = o;   // partial
            }
        }
    }
    __syncthreads();

    // ---- phase B: gin_b(ub); t2 = relu(partial + gb + b2b) -> sRG row-major ----
    copy_w(sW, W1b, tid);
    load_tileT(sRG, ub, row0, tid);
    __syncthreads();

    zero_acc(acc);
    gemm_layer_T(sRG, sW, rb, tc, acc);
    __syncthreads();

    relu_store_rm(acc, vb1b, sRG, rb, tc);
    copy_w(sW, W2b, tid);
    __syncthreads();

    zero_acc(acc);
    gemm_layer_rm(sRG, sW, rb, tc, acc);
    __syncthreads();                    // H reads done before overwriting with t2

    #pragma unroll
    for (int p = 0; p < 4; p++) {
        float2 v0 = unpack2(acc[p][0]);
        float2 v1 = unpack2(acc[p][1]);
        float2 v2 = unpack2(acc[p][2]);
        float2 v3 = unpack2(acc[p][3]);
        #pragma unroll
        for (int q = 0; q < 2; q++) {
            int r = rb + 2*p + q;
            int row = row0 + r;
            float4 pv = make_float4(0.f, 0.f, 0.f, 0.f);
            if (row < NN) pv = ((const float4*)ua)[(size_t)row*32 + tc];  // partial
            float4 o;
            o.x = fmaxf(pv.x + (q ? v0.y : v0.x) + vb2b.x, 0.f);
            o.y = fmaxf(pv.y + (q ? v1.y : v1.x) + vb2b.y, 0.f);
            o.z = fmaxf(pv.z + (q ? v2.y : v2.x) + vb2b.z, 0.f);
            o.w = fmaxf(pv.w + (q ? v3.y : v3.x) + vb2b.w, 0.f);
            *(float4*)&sRG[r*RMP + tc*4] = o;     // t2 row-major
        }
    }
    copy_w(sW, Wo, tid);
    __syncthreads();

    // ---- phase O: z = relu(t2@Wo + bo) in regs; LN via warp shuffles ----
    zero_acc(acc);
    gemm_layer_rm(sRG, sW, rb, tc, acc);

    float z8[8][4];
    #pragma unroll
    for (int p = 0; p < 4; p++) {
        float2 v0 = unpack2(acc[p][0]);
        float2 v1 = unpack2(acc[p][1]);
        float2 v2 = unpack2(acc[p][2]);
        float2 v3 = unpack2(acc[p][3]);
        z8[2*p  ][0] = fmaxf(v0.x + vbo.x, 0.f);
        z8[2*p+1][0] = fmaxf(v0.y + vbo.x, 0.f);
        z8[2*p  ][1] = fmaxf(v1.x + vbo.y, 0.f);
        z8[2*p+1][1] = fmaxf(v1.y + vbo.y, 0.f);
        z8[2*p  ][2] = fmaxf(v2.x + vbo.z, 0.f);
        z8[2*p+1][2] = fmaxf(v2.y + vbo.z, 0.f);
        z8[2*p  ][3] = fmaxf(v3.x + vbo.w, 0.f);
        z8[2*p+1][3] = fmaxf(v3.y + vbo.w, 0.f);
    }

    #pragma unroll
    for (int r = 0; r < 8; r++) {
        float s  = z8[r][0] + z8[r][1] + z8[r][2] + z8[r][3];
        float sq = z8[r][0]*z8[r][0] + z8[r][1]*z8[r][1]
                 + z8[r][2]*z8[r][2] + z8[r][3]*z8[r][3];
        #pragma unroll
        for (int d = 16; d > 0; d >>= 1) {
            s  += __shfl_xor_sync(0xffffffffu, s,  d);
            sq += __shfl_xor_sync(0xffffffffu, sq, d);
        }
        float m = s * (1.f/128.f);
        float var = sq * (1.f/128.f) - m*m;
        float rstd = rsqrtf(var + 1e-5f);
        int row = row0 + rb + r;
        if (row < NN) {
            float4 t2v = *(const float4*)&sRG[(rb + r)*RMP + tc*4];
            float4 o;
            o.x = t2v.x + (z8[r][0] - m)*rstd*vg.x + vbe.x;
            o.y = t2v.y + (z8[r][1] - m)*rstd*vg.y + vbe.y;
            o.z = t2v.z + (z8[r][2] - m)*rstd*vg.z + vbe.z;
            o.w = t2v.w + (z8[r][3] - m)*rstd*vg.w + vbe.w;
            ((float4*)OUT)[(size_t)row*32 + tc] = o;
        }
    }
}

// ---------------- launcher ----------------
extern "C" void kernel_launch(void* const* d_in, const int* in_sizes, int n_in,
                              void* d_out, int out_size) {
    const float* x   = (const float*)d_in[0];
    const float* t   = (const float*)d_in[1];
    const int*   et  = (const int*)d_in[2];
    const int*   ex  = (const int*)d_in[3];
    const float* W1a = (const float*)d_in[4];
    const float* b1a = (const float*)d_in[5];
    const float* W2a = (const float*)d_in[6];
    const float* b2a = (const float*)d_in[7];
    const float* W1b = (const float*)d_in[8];
    const float* b1b = (const float*)d_in[9];
    const float* W2b = (const float*)d_in[10];
    const float* b2b = (const float*)d_in[11];
    const float* Wo  = (const float*)d_in[12];
    const float* bo  = (const float*)d_in[13];
    const float* lng = (const float*)d_in[14];
    const float* lnb = (const float*)d_in[15];
    const float* Wf1 = (const float*)d_in[16];
    const float* bf1 = (const float*)d_in[17];
    const float* Wf2 = (const float*)d_in[18];
    const float* bf2 = (const float*)d_in[19];
    float* out = (float*)d_out;

    float *pua, *pub;
    cudaGetSymbolAddress((void**)&pua, g_ua);
    cudaGetSymbolAddress((void**)&pub, g_ub);

    cudaFuncSetAttribute(fc_x_kernel, cudaFuncAttributeMaxDynamicSharedMemorySize, SMEM_G_BYTES);
    cudaFuncSetAttribute(fused_t_kernel, cudaFuncAttributeMaxDynamicSharedMemorySize, SMEM_G_BYTES);

    // CSR build (fc_x placed 4th so the ncu capture lands on a GEMM kernel)
    zero_cnt_kernel<<<(TWO_N + 1023)/1024, 1024>>>();
    hist_kernel<<<(EE + 255)/256, 256>>>(et, ex);
    scan1_kernel<<<NSB, SCAN_B>>>();
    fc_x_kernel<<<NBLK, GT, SMEM_G_BYTES>>>(x, Wf1, bf1, Wf2, bf2, out);
    scan2_kernel<<<1, 256>>>();
    scan3_kernel<<<(TWO_N + 1 + 255)/256, 256>>>();
    fill_kernel<<<(EE + 255)/256, 256>>>(et, ex);

    // aggregate: ua = t + sum t[src] (e_t), ub = t + sum x[src] (e_xct)
    agg_kernel<<<(NN + 7)/8, 256>>>(x, t, pua, pub);

    // fused t-branch: gin_a + gin_b + t2 + out Linear + LayerNorm + residual
    fused_t_kernel<<<NBLK, GT, SMEM_G_BYTES>>>(pua, pub, t,
        W1a, b1a, W2a, b2a, W1b, b1b, W2b, b2b,
        Wo, bo, lng, lnb, out + (size_t)NN*DD);
}